// round 16
// baseline (speedup 1.0000x reference)
#include <cuda_runtime.h>
#include <math.h>
#include <stdint.h>

#define B_    256
#define NIN_  6912
#define SLOTS 8

typedef unsigned long long ull;

// ---------------- cp.async ----------------
__device__ __forceinline__ uint32_t s2u(const void* p) {
    return (uint32_t)__cvta_generic_to_shared(p);
}
__device__ __forceinline__ void cp16(const void* sdst, const void* gsrc) {
    asm volatile("cp.async.cg.shared.global [%0], [%1], 16;"
                 :: "r"(s2u(sdst)), "l"(gsrc) : "memory");
}
#define CP_COMMIT() asm volatile("cp.async.commit_group;" ::: "memory")
template <int N>
__device__ __forceinline__ void cp_wait() {
    asm volatile("cp.async.wait_group %0;" :: "n"(N) : "memory");
}

// ---------------- bf16 mma ----------------
__device__ __forceinline__ void bf16_split2(float vx, float vy,
                                            uint32_t& hi2, uint32_t& lo2) {
    asm("cvt.rn.bf16x2.f32 %0, %1, %2;" : "=r"(hi2) : "f"(vy), "f"(vx));
    float h0 = __uint_as_float(hi2 << 16);
    float h1 = __uint_as_float(hi2 & 0xffff0000u);
    float r0 = vx - h0, r1 = vy - h1;
    asm("cvt.rn.bf16x2.f32 %0, %1, %2;" : "=r"(lo2) : "f"(r1), "f"(r0));
}
__device__ __forceinline__ void mma_bf16_z(float* d, const uint32_t* a,
                                           uint32_t b0, uint32_t b1) {
    asm volatile(
        "mma.sync.aligned.m16n8k16.row.col.f32.bf16.bf16.f32 "
        "{%0,%1,%2,%3}, {%4,%5,%6,%7}, {%8,%9}, {%10,%10,%10,%10};"
        : "=f"(d[0]), "=f"(d[1]), "=f"(d[2]), "=f"(d[3])
        : "r"(a[0]), "r"(a[1]), "r"(a[2]), "r"(a[3]), "r"(b0), "r"(b1), "f"(0.0f));
}
__device__ __forceinline__ void mma_bf16(float* d, const uint32_t* a,
                                         uint32_t b0, uint32_t b1) {
    asm volatile(
        "mma.sync.aligned.m16n8k16.row.col.f32.bf16.bf16.f32 "
        "{%0,%1,%2,%3}, {%4,%5,%6,%7}, {%8,%9}, {%0,%1,%2,%3};"
        : "+f"(d[0]), "+f"(d[1]), "+f"(d[2]), "+f"(d[3])
        : "r"(a[0]), "r"(a[1]), "r"(a[2]), "r"(a[3]), "r"(b0), "r"(b1));
}

// ---------------- scratch (zero-initialized at load; each consumer re-zeroes) ---
__device__ float g_s1[SLOTS * B_ * 32];
__device__ float g_s2[SLOTS * B_ * 32];
__device__ __align__(16) float g_v1[B_ * 32];

__device__ __forceinline__ void squash16(const float* s, float* v) {
    float n2 = 0.0f;
#pragma unroll
    for (int e = 0; e < 16; ++e) n2 = fmaf(s[e], s[e], n2);
    float f = n2 / ((1.0f + n2) * sqrtf(n2 + 1e-9f));
#pragma unroll
    for (int e = 0; e < 16; ++e) v[e] = s[e] * f;
}

// Common tiling: block = 256 thr (8 warps), 128 b, 48 n = 12 stages x 4 n.
#define NPB   48
#define NST   4
#define NSTG  12
#define NBUF  3

#define XS_STRIDE 18432                     // 128*36*4 bytes
#define WT_OFF    (3 * XS_STRIDE)           // 55296
#define WT_STRIDE 4608                      // 32*36*4
#define WHI_OFF   (WT_OFF + 3 * WT_STRIDE)  // 69120
#define WLO_OFF   (WHI_OFF + 2048)
#define SMEM_TC   (WLO_OFF + 2048)          // 73216

// Shared staging: x f32 [128][36], W f32 [32][36] per buffer.
#define ISSUE_STAGE(s, n_base)                                                \
    do {                                                                      \
        const int buf_ = (s) % NBUF;                                          \
        const int n0_  = (n_base) + (s) * NST;                                \
        char* xd_ = sm + buf_ * XS_STRIDE;                                    \
        char* wd_ = sm + WT_OFF + buf_ * WT_STRIDE;                           \
        _Pragma("unroll")                                                     \
        for (int it_ = 0; it_ < 4; ++it_) {                                   \
            int f_ = it_ * 256 + tid;                                         \
            int bl_ = f_ >> 3, q_ = f_ & 7;                                   \
            cp16(xd_ + bl_ * 144 + q_ * 16,                                   \
                 X + ((size_t)(bB + bl_) * NIN_ + n0_) * 2 + q_);             \
        }                                                                     \
        {                                                                     \
            int j_ = tid >> 7, e_ = (tid >> 3) & 15,                          \
                nl_ = (tid >> 1) & 3, dh_ = tid & 1;                          \
            cp16(wd_ + ((j_ * 16 + e_) * 36 + nl_ * 8 + dh_ * 4) * 4,         \
                 Wg + ((size_t)(j_ * NIN_ + n0_ + nl_) * 16 + e_) * 2 + dh_); \
        }                                                                     \
        CP_COMMIT();                                                          \
    } while (0)

// W f32 stage -> bf16 hi/lo split, done once per block (shared).
#define CONVERT_W(s)                                                          \
    do {                                                                      \
        const int buf_ = (s) % NBUF;                                          \
        const float* wb_ = (const float*)(sm + WT_OFF + buf_ * WT_STRIDE);    \
        _Pragma("unroll")                                                     \
        for (int i_ = 0; i_ < 2; ++i_) {                                      \
            int u_ = tid * 2 + i_;                                            \
            int n_ = u_ >> 7, out_ = (u_ >> 2) & 31, c_ = u_ & 3;             \
            float w0_ = wb_[out_ * 36 + n_ * 8 + 2 * c_];                     \
            float w1_ = wb_[out_ * 36 + n_ * 8 + 2 * c_ + 1];                 \
            uint32_t h_, l_;                                                  \
            bf16_split2(w0_, w1_, h_, l_);                                    \
            Whi[n_ * 128 + out_ * 4 + c_] = h_;                               \
            Wlo[n_ * 128 + out_ * 4 + c_] = l_;                               \
        }                                                                     \
    } while (0)

// =================================================================
// Pass 1 (bf16 K-half MMA): S1 tile accumulated in D fragments.
// =================================================================
__global__ __launch_bounds__(256, 2) void pass1_tc(const float4* __restrict__ X,
                                                   const float4* __restrict__ Wg) {
    extern __shared__ char sm[];
    const int tid  = threadIdx.x;
    const int wid  = tid >> 5;
    const int lane = tid & 31;
    const int cc   = lane & 3;
    const int rr   = lane >> 2;
    const int bB   = blockIdx.y * 128;
    const int nbase = blockIdx.x * NPB;

    uint32_t* Whi = (uint32_t*)(sm + WHI_OFF);
    uint32_t* Wlo = (uint32_t*)(sm + WLO_OFF);

    float acc[4][4];
#pragma unroll
    for (int nt = 0; nt < 4; ++nt)
#pragma unroll
        for (int i = 0; i < 4; ++i) acc[nt][i] = 0.0f;

    ISSUE_STAGE(0, nbase);
    ISSUE_STAGE(1, nbase);
#pragma unroll 3
    for (int s = 0; s < NSTG; ++s) {
        cp_wait<1>();
        __syncthreads();
        CONVERT_W(s);
        __syncthreads();
        if (s + 2 < NSTG) { ISSUE_STAGE(s + 2, nbase); } else { CP_COMMIT(); }

        const int buf = s % NBUF;
        const float* xb = (const float*)(sm + buf * XS_STRIDE);
        const int rA = wid * 16 + rr;
#pragma unroll
        for (int nl = 0; nl < NST; ++nl) {
            float x0 = xb[rA * 36 + nl * 8 + 2 * cc];
            float x1 = xb[rA * 36 + nl * 8 + 2 * cc + 1];
            float y0 = xb[(rA + 8) * 36 + nl * 8 + 2 * cc];
            float y1 = xb[(rA + 8) * 36 + nl * 8 + 2 * cc + 1];
            uint32_t a[4];
            bf16_split2(x0, x1, a[0], a[2]);   // hi in k0-7, lo in k8-15
            bf16_split2(y0, y1, a[1], a[3]);
#pragma unroll
            for (int nt = 0; nt < 4; ++nt) {
                uint32_t bh = Whi[nl * 128 + (nt * 8 + rr) * 4 + cc];
                uint32_t bl = Wlo[nl * 128 + (nt * 8 + rr) * 4 + cc];
                mma_bf16(acc[nt], a, bh, bh);  // (Ahi+Alo).Bhi, accumulate
                mma_bf16(acc[nt], a, bl, bl);  // + (Ahi+Alo).Blo
            }
        }
    }

    float* dst = g_s1 + (blockIdx.x & (SLOTS - 1)) * (B_ * 32);
    const int r0 = bB + wid * 16 + rr;
    const int c0base = cc * 2;
#pragma unroll
    for (int nt = 0; nt < 4; ++nt) {
        const int col = nt * 8 + c0base;
        atomicAdd(dst + col * B_ + r0,           acc[nt][0]);
        atomicAdd(dst + (col + 1) * B_ + r0,     acc[nt][1]);
        atomicAdd(dst + col * B_ + r0 + 8,       acc[nt][2]);
        atomicAdd(dst + (col + 1) * B_ + r0 + 8, acc[nt][3]);
    }
}

// ======= v1 = squash(0.5 * sum_slots s1); re-zero g_s1 for next replay =======
__global__ void v1_kernel() {
    __shared__ float s[32][B_];
    const int tid = threadIdx.x;
    const int b   = tid & 255;
    const int kg  = tid >> 8;
#pragma unroll
    for (int i = 0; i < 8; ++i) {
        int k = kg * 8 + i;
        float a = 0.0f;
#pragma unroll
        for (int sl = 0; sl < SLOTS; ++sl) {
            a += g_s1[sl * (B_ * 32) + k * B_ + b];
            g_s1[sl * (B_ * 32) + k * B_ + b] = 0.0f;
        }
        s[k][b] = a * 0.5f;
    }
    __syncthreads();
    if (tid < 512) {
        int bb = tid >> 1, j = tid & 1;
        float sv[16], v[16];
#pragma unroll
        for (int e = 0; e < 16; ++e) sv[e] = s[j * 16 + e][bb];
        squash16(sv, v);
#pragma unroll
        for (int e = 0; e < 16; ++e) g_v1[bb * 32 + j * 16 + e] = v[e];
    }
}

// =================================================================
// Pass 2 (bf16 K-half MMA + fragment routing) — round-15 version.
// =================================================================
__global__ __launch_bounds__(256, 2) void pass2_tc(const float4* __restrict__ X,
                                                   const float4* __restrict__ Wg) {
    extern __shared__ char sm[];
    const int tid  = threadIdx.x;
    const int wid  = tid >> 5;
    const int lane = tid & 31;
    const int cc   = lane & 3;
    const int rr   = lane >> 2;
    const int bB   = blockIdx.y * 128;
    const int nbase = blockIdx.x * NPB;

    uint32_t* Whi = (uint32_t*)(sm + WHI_OFF);
    uint32_t* Wlo = (uint32_t*)(sm + WLO_OFF);

    const int r0 = bB + wid * 16 + rr;
    float v1f[2][4][2];
#pragma unroll
    for (int i = 0; i < 2; ++i)
#pragma unroll
        for (int nt = 0; nt < 4; ++nt) {
            v1f[i][nt][0] = g_v1[(r0 + i * 8) * 32 + nt * 8 + 2 * cc];
            v1f[i][nt][1] = g_v1[(r0 + i * 8) * 32 + nt * 8 + 2 * cc + 1];
        }

    float sacc[4][4];
#pragma unroll
    for (int nt = 0; nt < 4; ++nt)
#pragma unroll
        for (int i = 0; i < 4; ++i) sacc[nt][i] = 0.0f;

    ISSUE_STAGE(0, nbase);
    ISSUE_STAGE(1, nbase);
#pragma unroll 3
    for (int s = 0; s < NSTG; ++s) {
        cp_wait<1>();
        __syncthreads();
        CONVERT_W(s);
        __syncthreads();
        if (s + 2 < NSTG) { ISSUE_STAGE(s + 2, nbase); } else { CP_COMMIT(); }

        const int buf = s % NBUF;
        const float* xb = (const float*)(sm + buf * XS_STRIDE);
        const int rA = wid * 16 + rr;
#pragma unroll
        for (int nl = 0; nl < NST; ++nl) {
            float x0 = xb[rA * 36 + nl * 8 + 2 * cc];
            float x1 = xb[rA * 36 + nl * 8 + 2 * cc + 1];
            float y0 = xb[(rA + 8) * 36 + nl * 8 + 2 * cc];
            float y1 = xb[(rA + 8) * 36 + nl * 8 + 2 * cc + 1];
            uint32_t a[4];
            bf16_split2(x0, x1, a[0], a[2]);
            bf16_split2(y0, y1, a[1], a[3]);

            float u[4][4];
#pragma unroll
            for (int nt = 0; nt < 4; ++nt) {
                uint32_t bh = Whi[nl * 128 + (nt * 8 + rr) * 4 + cc];
                uint32_t bl = Wlo[nl * 128 + (nt * 8 + rr) * 4 + cc];
                mma_bf16_z(u[nt], a, bh, bh);
                mma_bf16(u[nt], a, bl, bl);
            }

            float t00 = 0.f, t01 = 0.f, t10 = 0.f, t11 = 0.f;
#pragma unroll
            for (int nt = 0; nt < 4; ++nt) {
                float p0 = fmaf(v1f[0][nt][0], u[nt][0],
                                v1f[0][nt][1] * u[nt][1]);
                float p1 = fmaf(v1f[1][nt][0], u[nt][2],
                                v1f[1][nt][1] * u[nt][3]);
                if (nt < 2) { t00 += p0; t10 += p1; }
                else        { t01 += p0; t11 += p1; }
            }
#pragma unroll
            for (int st = 1; st <= 2; st <<= 1) {
                t00 += __shfl_xor_sync(0xffffffffu, t00, st);
                t01 += __shfl_xor_sync(0xffffffffu, t01, st);
                t10 += __shfl_xor_sync(0xffffffffu, t10, st);
                t11 += __shfl_xor_sync(0xffffffffu, t11, st);
            }
            float c0a = __fdividef(1.0f, 1.0f + __expf(t01 - t00));
            float c0b = __fdividef(1.0f, 1.0f + __expf(t11 - t10));
            float c1a = 1.0f - c0a;
            float c1b = 1.0f - c0b;
#pragma unroll
            for (int nt = 0; nt < 4; ++nt) {
                float ca = (nt < 2) ? c0a : c1a;
                float cb = (nt < 2) ? c0b : c1b;
                sacc[nt][0] = fmaf(ca, u[nt][0], sacc[nt][0]);
                sacc[nt][1] = fmaf(ca, u[nt][1], sacc[nt][1]);
                sacc[nt][2] = fmaf(cb, u[nt][2], sacc[nt][2]);
                sacc[nt][3] = fmaf(cb, u[nt][3], sacc[nt][3]);
            }
        }
    }

    float* dst = g_s2 + (blockIdx.x & (SLOTS - 1)) * (B_ * 32);
    const int c0base = cc * 2;
#pragma unroll
    for (int nt = 0; nt < 4; ++nt) {
        const int col = nt * 8 + c0base;
        atomicAdd(dst + col * B_ + r0,           sacc[nt][0]);
        atomicAdd(dst + (col + 1) * B_ + r0,     sacc[nt][1]);
        atomicAdd(dst + col * B_ + r0 + 8,       sacc[nt][2]);
        atomicAdd(dst + (col + 1) * B_ + r0 + 8, sacc[nt][3]);
    }
}

// ===== Output: v = squash(sum_slots s2); re-zero g_s2 for next replay =====
__global__ void squash_out_kernel(float* __restrict__ out) {
    __shared__ float s[32][B_];
    const int tid = threadIdx.x;
    const int b   = tid & 255;
    const int kg  = tid >> 8;
#pragma unroll
    for (int i = 0; i < 8; ++i) {
        int k = kg * 8 + i;
        float a = 0.0f;
#pragma unroll
        for (int sl = 0; sl < SLOTS; ++sl) {
            a += g_s2[sl * (B_ * 32) + k * B_ + b];
            g_s2[sl * (B_ * 32) + k * B_ + b] = 0.0f;
        }
        s[k][b] = a;
    }
    __syncthreads();
    if (tid < 512) {
        int bb = tid >> 1, j = tid & 1;
        float sv[16], v[16];
#pragma unroll
        for (int e = 0; e < 16; ++e) sv[e] = s[j * 16 + e][bb];
        squash16(sv, v);
#pragma unroll
        for (int e = 0; e < 16; ++e) out[bb * 32 + j * 16 + e] = v[e];
    }
}

extern "C" void kernel_launch(void* const* d_in, const int* in_sizes, int n_in,
                              void* d_out, int out_size) {
    const float4* X = (const float4*)d_in[0];   // x: [256, 6912, 8] f32
    const float4* W = (const float4*)d_in[1];   // W: [2, 6912, 16, 8] f32
    float* out = (float*)d_out;                 // v: [256, 2, 16] f32

    cudaFuncSetAttribute(pass1_tc, cudaFuncAttributeMaxDynamicSharedMemorySize, SMEM_TC);
    cudaFuncSetAttribute(pass2_tc, cudaFuncAttributeMaxDynamicSharedMemorySize, SMEM_TC);

    dim3 g(NIN_ / NPB, 2);                 // 144 x 2 = 288 blocks
    pass1_tc<<<g, 256, SMEM_TC>>>(X, W);
    v1_kernel<<<1, 1024>>>();
    pass2_tc<<<g, 256, SMEM_TC>>>(X, W);
    squash_out_kernel<<<1, 1024>>>(out);
}

// round 17
// speedup vs baseline: 1.0705x; 1.0705x over previous
#include <cuda_runtime.h>
#include <math.h>
#include <stdint.h>

#define B_    256
#define NIN_  6912
#define SLOTS 8

typedef unsigned long long ull;

// ---------------- cp.async ----------------
__device__ __forceinline__ uint32_t s2u(const void* p) {
    return (uint32_t)__cvta_generic_to_shared(p);
}
__device__ __forceinline__ void cp16(const void* sdst, const void* gsrc) {
    asm volatile("cp.async.cg.shared.global [%0], [%1], 16;"
                 :: "r"(s2u(sdst)), "l"(gsrc) : "memory");
}
#define CP_COMMIT() asm volatile("cp.async.commit_group;" ::: "memory")
template <int N>
__device__ __forceinline__ void cp_wait() {
    asm volatile("cp.async.wait_group %0;" :: "n"(N) : "memory");
}

// ---------------- bf16 mma ----------------
__device__ __forceinline__ void bf16_split2(float vx, float vy,
                                            uint32_t& hi2, uint32_t& lo2) {
    asm("cvt.rn.bf16x2.f32 %0, %1, %2;" : "=r"(hi2) : "f"(vy), "f"(vx));
    float h0 = __uint_as_float(hi2 << 16);
    float h1 = __uint_as_float(hi2 & 0xffff0000u);
    float r0 = vx - h0, r1 = vy - h1;
    asm("cvt.rn.bf16x2.f32 %0, %1, %2;" : "=r"(lo2) : "f"(r1), "f"(r0));
}
__device__ __forceinline__ void mma_bf16_z(float* d, const uint32_t* a,
                                           uint32_t b0, uint32_t b1) {
    asm volatile(
        "mma.sync.aligned.m16n8k16.row.col.f32.bf16.bf16.f32 "
        "{%0,%1,%2,%3}, {%4,%5,%6,%7}, {%8,%9}, {%10,%10,%10,%10};"
        : "=f"(d[0]), "=f"(d[1]), "=f"(d[2]), "=f"(d[3])
        : "r"(a[0]), "r"(a[1]), "r"(a[2]), "r"(a[3]), "r"(b0), "r"(b1), "f"(0.0f));
}
__device__ __forceinline__ void mma_bf16(float* d, const uint32_t* a,
                                         uint32_t b0, uint32_t b1) {
    asm volatile(
        "mma.sync.aligned.m16n8k16.row.col.f32.bf16.bf16.f32 "
        "{%0,%1,%2,%3}, {%4,%5,%6,%7}, {%8,%9}, {%0,%1,%2,%3};"
        : "+f"(d[0]), "+f"(d[1]), "+f"(d[2]), "+f"(d[3])
        : "r"(a[0]), "r"(a[1]), "r"(a[2]), "r"(a[3]), "r"(b0), "r"(b1));
}

// ---------------- scratch (zeroed at load; trailing kernel re-zeroes) ----------
__device__ float g_s1[SLOTS * B_ * 32];
__device__ float g_s2[SLOTS * B_ * 32];
__device__ __align__(16) float g_v1[B_ * 32];

__device__ __forceinline__ void squash16(const float* s, float* v) {
    float n2 = 0.0f;
#pragma unroll
    for (int e = 0; e < 16; ++e) n2 = fmaf(s[e], s[e], n2);
    float f = n2 / ((1.0f + n2) * sqrtf(n2 + 1e-9f));
#pragma unroll
    for (int e = 0; e < 16; ++e) v[e] = s[e] * f;
}

// Common tiling: block = 256 thr (8 warps), 128 b, 48 n = 12 stages x 4 n.
#define NPB   48
#define NST   4
#define NSTG  12
#define NBUF  3

#define XS_STRIDE 18432                     // 128*36*4 bytes
#define WT_OFF    (3 * XS_STRIDE)           // 55296
#define WT_STRIDE 4608                      // 32*36*4
#define WHI_OFF   (WT_OFF + 3 * WT_STRIDE)  // 69120
#define WLO_OFF   (WHI_OFF + 2048)
#define SMEM_TC   (WLO_OFF + 2048)          // 73216

#define ISSUE_STAGE(s, n_base)                                                \
    do {                                                                      \
        const int buf_ = (s) % NBUF;                                          \
        const int n0_  = (n_base) + (s) * NST;                                \
        char* xd_ = sm + buf_ * XS_STRIDE;                                    \
        char* wd_ = sm + WT_OFF + buf_ * WT_STRIDE;                           \
        _Pragma("unroll")                                                     \
        for (int it_ = 0; it_ < 4; ++it_) {                                   \
            int f_ = it_ * 256 + tid;                                         \
            int bl_ = f_ >> 3, q_ = f_ & 7;                                   \
            cp16(xd_ + bl_ * 144 + q_ * 16,                                   \
                 X + ((size_t)(bB + bl_) * NIN_ + n0_) * 2 + q_);             \
        }                                                                     \
        {                                                                     \
            int j_ = tid >> 7, e_ = (tid >> 3) & 15,                          \
                nl_ = (tid >> 1) & 3, dh_ = tid & 1;                          \
            cp16(wd_ + ((j_ * 16 + e_) * 36 + nl_ * 8 + dh_ * 4) * 4,         \
                 Wg + ((size_t)(j_ * NIN_ + n0_ + nl_) * 16 + e_) * 2 + dh_); \
        }                                                                     \
        CP_COMMIT();                                                          \
    } while (0)

#define CONVERT_W(s)                                                          \
    do {                                                                      \
        const int buf_ = (s) % NBUF;                                          \
        const float* wb_ = (const float*)(sm + WT_OFF + buf_ * WT_STRIDE);    \
        _Pragma("unroll")                                                     \
        for (int i_ = 0; i_ < 2; ++i_) {                                      \
            int u_ = tid * 2 + i_;                                            \
            int n_ = u_ >> 7, out_ = (u_ >> 2) & 31, c_ = u_ & 3;             \
            float w0_ = wb_[out_ * 36 + n_ * 8 + 2 * c_];                     \
            float w1_ = wb_[out_ * 36 + n_ * 8 + 2 * c_ + 1];                 \
            uint32_t h_, l_;                                                  \
            bf16_split2(w0_, w1_, h_, l_);                                    \
            Whi[n_ * 128 + out_ * 4 + c_] = h_;                               \
            Wlo[n_ * 128 + out_ * 4 + c_] = l_;                               \
        }                                                                     \
    } while (0)

// =================================================================
// Pass 1 (bf16 K-half MMA)
// =================================================================
__global__ __launch_bounds__(256, 2) void pass1_tc(const float4* __restrict__ X,
                                                   const float4* __restrict__ Wg) {
    extern __shared__ char sm[];
    const int tid  = threadIdx.x;
    const int wid  = tid >> 5;
    const int lane = tid & 31;
    const int cc   = lane & 3;
    const int rr   = lane >> 2;
    const int bB   = blockIdx.y * 128;
    const int nbase = blockIdx.x * NPB;

    uint32_t* Whi = (uint32_t*)(sm + WHI_OFF);
    uint32_t* Wlo = (uint32_t*)(sm + WLO_OFF);

    float acc[4][4];
#pragma unroll
    for (int nt = 0; nt < 4; ++nt)
#pragma unroll
        for (int i = 0; i < 4; ++i) acc[nt][i] = 0.0f;

    ISSUE_STAGE(0, nbase);
    ISSUE_STAGE(1, nbase);
#pragma unroll 3
    for (int s = 0; s < NSTG; ++s) {
        cp_wait<1>();
        __syncthreads();
        CONVERT_W(s);
        __syncthreads();
        if (s + 2 < NSTG) { ISSUE_STAGE(s + 2, nbase); } else { CP_COMMIT(); }

        const int buf = s % NBUF;
        const float* xb = (const float*)(sm + buf * XS_STRIDE);
        const int rA = wid * 16 + rr;
#pragma unroll
        for (int nl = 0; nl < NST; ++nl) {
            float x0 = xb[rA * 36 + nl * 8 + 2 * cc];
            float x1 = xb[rA * 36 + nl * 8 + 2 * cc + 1];
            float y0 = xb[(rA + 8) * 36 + nl * 8 + 2 * cc];
            float y1 = xb[(rA + 8) * 36 + nl * 8 + 2 * cc + 1];
            uint32_t a[4];
            bf16_split2(x0, x1, a[0], a[2]);
            bf16_split2(y0, y1, a[1], a[3]);
#pragma unroll
            for (int nt = 0; nt < 4; ++nt) {
                uint32_t bh = Whi[nl * 128 + (nt * 8 + rr) * 4 + cc];
                uint32_t bl = Wlo[nl * 128 + (nt * 8 + rr) * 4 + cc];
                mma_bf16(acc[nt], a, bh, bh);
                mma_bf16(acc[nt], a, bl, bl);
            }
        }
    }

    float* dst = g_s1 + (blockIdx.x & (SLOTS - 1)) * (B_ * 32);
    const int r0 = bB + wid * 16 + rr;
    const int c0base = cc * 2;
#pragma unroll
    for (int nt = 0; nt < 4; ++nt) {
        const int col = nt * 8 + c0base;
        atomicAdd(dst + col * B_ + r0,           acc[nt][0]);
        atomicAdd(dst + (col + 1) * B_ + r0,     acc[nt][1]);
        atomicAdd(dst + col * B_ + r0 + 8,       acc[nt][2]);
        atomicAdd(dst + (col + 1) * B_ + r0 + 8, acc[nt][3]);
    }
}

// ======= v1 = squash(0.5 * sum_slots s1) (read-only on g_s1) =======
__global__ void v1_kernel() {
    __shared__ float s[32][B_];
    const int tid = threadIdx.x;
    const int b   = tid & 255;
    const int kg  = tid >> 8;
#pragma unroll
    for (int i = 0; i < 8; ++i) {
        int k = kg * 8 + i;
        float a = 0.0f;
#pragma unroll
        for (int sl = 0; sl < SLOTS; ++sl)
            a += g_s1[sl * (B_ * 32) + k * B_ + b];
        s[k][b] = a * 0.5f;
    }
    __syncthreads();
    if (tid < 512) {
        int bb = tid >> 1, j = tid & 1;
        float sv[16], v[16];
#pragma unroll
        for (int e = 0; e < 16; ++e) sv[e] = s[j * 16 + e][bb];
        squash16(sv, v);
#pragma unroll
        for (int e = 0; e < 16; ++e) g_v1[bb * 32 + j * 16 + e] = v[e];
    }
}

// =================================================================
// Pass 2 (bf16 K-half MMA + fragment routing)
// =================================================================
__global__ __launch_bounds__(256, 2) void pass2_tc(const float4* __restrict__ X,
                                                   const float4* __restrict__ Wg) {
    extern __shared__ char sm[];
    const int tid  = threadIdx.x;
    const int wid  = tid >> 5;
    const int lane = tid & 31;
    const int cc   = lane & 3;
    const int rr   = lane >> 2;
    const int bB   = blockIdx.y * 128;
    const int nbase = blockIdx.x * NPB;

    uint32_t* Whi = (uint32_t*)(sm + WHI_OFF);
    uint32_t* Wlo = (uint32_t*)(sm + WLO_OFF);

    const int r0 = bB + wid * 16 + rr;
    float v1f[2][4][2];
#pragma unroll
    for (int i = 0; i < 2; ++i)
#pragma unroll
        for (int nt = 0; nt < 4; ++nt) {
            v1f[i][nt][0] = g_v1[(r0 + i * 8) * 32 + nt * 8 + 2 * cc];
            v1f[i][nt][1] = g_v1[(r0 + i * 8) * 32 + nt * 8 + 2 * cc + 1];
        }

    float sacc[4][4];
#pragma unroll
    for (int nt = 0; nt < 4; ++nt)
#pragma unroll
        for (int i = 0; i < 4; ++i) sacc[nt][i] = 0.0f;

    ISSUE_STAGE(0, nbase);
    ISSUE_STAGE(1, nbase);
#pragma unroll 3
    for (int s = 0; s < NSTG; ++s) {
        cp_wait<1>();
        __syncthreads();
        CONVERT_W(s);
        __syncthreads();
        if (s + 2 < NSTG) { ISSUE_STAGE(s + 2, nbase); } else { CP_COMMIT(); }

        const int buf = s % NBUF;
        const float* xb = (const float*)(sm + buf * XS_STRIDE);
        const int rA = wid * 16 + rr;
#pragma unroll
        for (int nl = 0; nl < NST; ++nl) {
            float x0 = xb[rA * 36 + nl * 8 + 2 * cc];
            float x1 = xb[rA * 36 + nl * 8 + 2 * cc + 1];
            float y0 = xb[(rA + 8) * 36 + nl * 8 + 2 * cc];
            float y1 = xb[(rA + 8) * 36 + nl * 8 + 2 * cc + 1];
            uint32_t a[4];
            bf16_split2(x0, x1, a[0], a[2]);
            bf16_split2(y0, y1, a[1], a[3]);

            float u[4][4];
#pragma unroll
            for (int nt = 0; nt < 4; ++nt) {
                uint32_t bh = Whi[nl * 128 + (nt * 8 + rr) * 4 + cc];
                uint32_t bl = Wlo[nl * 128 + (nt * 8 + rr) * 4 + cc];
                mma_bf16_z(u[nt], a, bh, bh);
                mma_bf16(u[nt], a, bl, bl);
            }

            float t00 = 0.f, t01 = 0.f, t10 = 0.f, t11 = 0.f;
#pragma unroll
            for (int nt = 0; nt < 4; ++nt) {
                float p0 = fmaf(v1f[0][nt][0], u[nt][0],
                                v1f[0][nt][1] * u[nt][1]);
                float p1 = fmaf(v1f[1][nt][0], u[nt][2],
                                v1f[1][nt][1] * u[nt][3]);
                if (nt < 2) { t00 += p0; t10 += p1; }
                else        { t01 += p0; t11 += p1; }
            }
#pragma unroll
            for (int st = 1; st <= 2; st <<= 1) {
                t00 += __shfl_xor_sync(0xffffffffu, t00, st);
                t01 += __shfl_xor_sync(0xffffffffu, t01, st);
                t10 += __shfl_xor_sync(0xffffffffu, t10, st);
                t11 += __shfl_xor_sync(0xffffffffu, t11, st);
            }
            float c0a = __fdividef(1.0f, 1.0f + __expf(t01 - t00));
            float c0b = __fdividef(1.0f, 1.0f + __expf(t11 - t10));
            float c1a = 1.0f - c0a;
            float c1b = 1.0f - c0b;
#pragma unroll
            for (int nt = 0; nt < 4; ++nt) {
                float ca = (nt < 2) ? c0a : c1a;
                float cb = (nt < 2) ? c0b : c1b;
                sacc[nt][0] = fmaf(ca, u[nt][0], sacc[nt][0]);
                sacc[nt][1] = fmaf(ca, u[nt][1], sacc[nt][1]);
                sacc[nt][2] = fmaf(cb, u[nt][2], sacc[nt][2]);
                sacc[nt][3] = fmaf(cb, u[nt][3], sacc[nt][3]);
            }
        }
    }

    float* dst = g_s2 + (blockIdx.x & (SLOTS - 1)) * (B_ * 32);
    const int c0base = cc * 2;
#pragma unroll
    for (int nt = 0; nt < 4; ++nt) {
        const int col = nt * 8 + c0base;
        atomicAdd(dst + col * B_ + r0,           sacc[nt][0]);
        atomicAdd(dst + (col + 1) * B_ + r0,     sacc[nt][1]);
        atomicAdd(dst + col * B_ + r0 + 8,       sacc[nt][2]);
        atomicAdd(dst + (col + 1) * B_ + r0 + 8, sacc[nt][3]);
    }
}

// ===== Output: v = squash(sum_slots s2) (read-only on g_s2) =====
__global__ void squash_out_kernel(float* __restrict__ out) {
    __shared__ float s[32][B_];
    const int tid = threadIdx.x;
    const int b   = tid & 255;
    const int kg  = tid >> 8;
#pragma unroll
    for (int i = 0; i < 8; ++i) {
        int k = kg * 8 + i;
        float a = 0.0f;
#pragma unroll
        for (int sl = 0; sl < SLOTS; ++sl)
            a += g_s2[sl * (B_ * 32) + k * B_ + b];
        s[k][b] = a;
    }
    __syncthreads();
    if (tid < 512) {
        int bb = tid >> 1, j = tid & 1;
        float sv[16], v[16];
#pragma unroll
        for (int e = 0; e < 16; ++e) sv[e] = s[j * 16 + e][bb];
        squash16(sv, v);
#pragma unroll
        for (int e = 0; e < 16; ++e) out[bb * 32 + j * 16 + e] = v[e];
    }
}

// Trailing zero: restores invariant "scratch is zero at kernel_launch entry".
__global__ void zero_tail_kernel() {
    int i = blockIdx.x * blockDim.x + threadIdx.x;
    if (i < SLOTS * B_ * 32) { g_s1[i] = 0.0f; g_s2[i] = 0.0f; }
}

extern "C" void kernel_launch(void* const* d_in, const int* in_sizes, int n_in,
                              void* d_out, int out_size) {
    const float4* X = (const float4*)d_in[0];   // x: [256, 6912, 8] f32
    const float4* W = (const float4*)d_in[1];   // W: [2, 6912, 16, 8] f32
    float* out = (float*)d_out;                 // v: [256, 2, 16] f32

    cudaFuncSetAttribute(pass1_tc, cudaFuncAttributeMaxDynamicSharedMemorySize, SMEM_TC);
    cudaFuncSetAttribute(pass2_tc, cudaFuncAttributeMaxDynamicSharedMemorySize, SMEM_TC);

    dim3 g(NIN_ / NPB, 2);                 // 144 x 2 = 288 blocks
    pass1_tc<<<g, 256, SMEM_TC>>>(X, W);
    v1_kernel<<<1, 1024>>>();
    pass2_tc<<<g, 256, SMEM_TC>>>(X, W);
    squash_out_kernel<<<1, 1024>>>(out);
    zero_tail_kernel<<<(SLOTS * B_ * 32 + 255) / 256, 256>>>();
}